// round 1
// baseline (speedup 1.0000x reference)
#include <cuda_runtime.h>
#include <math.h>

#define N_NODES 50000
#define N_EDGES 800000
#define D 128
#define GEMM_NODES 16

// Scratch (device globals: no allocation allowed in kernel_launch)
__device__ float g_z[N_NODES * D];      // 25.6 MB mixed accumulator
__device__ float g_alpha[N_NODES];
__device__ float g_Wt[D * D];           // W transposed: [k][o]

__global__ void zero_z_kernel() {
    int idx = blockIdx.x * blockDim.x + threadIdx.x;
    float4* p = reinterpret_cast<float4*>(g_z);
    const int n4 = N_NODES * D / 4;
    for (int i = idx; i < n4; i += gridDim.x * blockDim.x)
        p[i] = make_float4(0.f, 0.f, 0.f, 0.f);
}

__global__ void transpose_W_kernel(const float* __restrict__ W) {
    int idx = blockIdx.x * blockDim.x + threadIdx.x;
    if (idx < D * D) {
        int k = idx / D, o = idx % D;
        g_Wt[idx] = W[o * D + k];   // write coalesced, read strided (tiny, cached)
    }
}

// One warp per node: alpha = sigmoid(x . theta + b)
__global__ void alpha_kernel(const float* __restrict__ x,
                             const float* __restrict__ aw,
                             const float* __restrict__ ab,
                             float* __restrict__ out_alpha, int write_alpha) {
    int warp = (blockIdx.x * blockDim.x + threadIdx.x) >> 5;
    int lane = threadIdx.x & 31;
    if (warp >= N_NODES) return;
    float4 xv = *reinterpret_cast<const float4*>(x + (size_t)warp * D + lane * 4);
    float4 wv = *reinterpret_cast<const float4*>(aw + lane * 4);
    float s = xv.x * wv.x + xv.y * wv.y + xv.z * wv.z + xv.w * wv.w;
    #pragma unroll
    for (int off = 16; off; off >>= 1) s += __shfl_xor_sync(0xffffffffu, s, off);
    if (lane == 0) {
        float a = 1.f / (1.f + expf(-(s + ab[0])));
        g_alpha[warp] = a;
        if (write_alpha) out_alpha[warp] = a;
    }
}

// One warp per edge (both operators fused): z[row] += coef * x[col]
// coef = alpha[row]*val (lp)  or  (1-alpha[row])*val (hp)
__global__ void edge_scatter_kernel(const float* __restrict__ x,
                                    const int* __restrict__ lp_rows,
                                    const int* __restrict__ lp_cols,
                                    const float* __restrict__ lp_vals,
                                    const int* __restrict__ hp_rows,
                                    const int* __restrict__ hp_cols,
                                    const float* __restrict__ hp_vals) {
    long long warp = ((long long)blockIdx.x * blockDim.x + threadIdx.x) >> 5;
    int lane = threadIdx.x & 31;
    if (warp >= 2LL * N_EDGES) return;

    int e; int row, col; float v; bool hp;
    if (warp >= N_EDGES) {
        e = (int)(warp - N_EDGES);
        row = hp_rows[e]; col = hp_cols[e]; v = hp_vals[e]; hp = true;
    } else {
        e = (int)warp;
        row = lp_rows[e]; col = lp_cols[e]; v = lp_vals[e]; hp = false;
    }
    float a = g_alpha[row];
    float coef = hp ? (1.f - a) * v : a * v;

    float4 xv = *reinterpret_cast<const float4*>(x + (size_t)col * D + lane * 4);
    float* zp = g_z + (size_t)row * D + lane * 4;
    atomicAdd(zp + 0, coef * xv.x);
    atomicAdd(zp + 1, coef * xv.y);
    atomicAdd(zp + 2, coef * xv.z);
    atomicAdd(zp + 3, coef * xv.w);
}

// out[n][o] = relu(sum_k z[n][k] * Wt[k][o] + b[o])
// Block: 256 threads, 16 nodes, full 128 output cols. W^T staged in shared.
// Thread micro-tile: 2 nodes x 4 cols, k-loop with LDS128 on W^T rows.
extern __shared__ float g_smem[];
__global__ void gemm_relu_kernel(const float* __restrict__ bias,
                                 float* __restrict__ out) {
    float* wt_sh = g_smem;              // 128*128 floats
    float* z_sh  = g_smem + D * D;      // 16*128 floats
    int tid = threadIdx.x;

    {
        const float4* src = reinterpret_cast<const float4*>(g_Wt);
        float4* dst = reinterpret_cast<float4*>(wt_sh);
        #pragma unroll
        for (int i = tid; i < D * D / 4; i += 256) dst[i] = src[i];
    }
    int node_base = blockIdx.x * GEMM_NODES;
    {
        const float4* src = reinterpret_cast<const float4*>(g_z + (size_t)node_base * D);
        float4* dst = reinterpret_cast<float4*>(z_sh);
        #pragma unroll
        for (int i = tid; i < GEMM_NODES * D / 4; i += 256) dst[i] = src[i];
    }
    __syncthreads();

    int o_base = (tid & 31) * 4;
    int ng = tid >> 5;          // 0..7
    int n0 = ng * 2, n1 = n0 + 1;
    const float* z0p = z_sh + n0 * D;
    const float* z1p = z_sh + n1 * D;

    float acc00 = 0.f, acc01 = 0.f, acc02 = 0.f, acc03 = 0.f;
    float acc10 = 0.f, acc11 = 0.f, acc12 = 0.f, acc13 = 0.f;

    #pragma unroll 8
    for (int k = 0; k < D; k++) {
        float4 w = *reinterpret_cast<const float4*>(wt_sh + k * D + o_base);
        float z0 = z0p[k], z1 = z1p[k];
        acc00 += z0 * w.x; acc01 += z0 * w.y; acc02 += z0 * w.z; acc03 += z0 * w.w;
        acc10 += z1 * w.x; acc11 += z1 * w.y; acc12 += z1 * w.z; acc13 += z1 * w.w;
    }

    float4 bv = *reinterpret_cast<const float4*>(bias + o_base);
    float4 r0, r1;
    r0.x = fmaxf(acc00 + bv.x, 0.f); r0.y = fmaxf(acc01 + bv.y, 0.f);
    r0.z = fmaxf(acc02 + bv.z, 0.f); r0.w = fmaxf(acc03 + bv.w, 0.f);
    r1.x = fmaxf(acc10 + bv.x, 0.f); r1.y = fmaxf(acc11 + bv.y, 0.f);
    r1.z = fmaxf(acc12 + bv.z, 0.f); r1.w = fmaxf(acc13 + bv.w, 0.f);

    *reinterpret_cast<float4*>(out + (size_t)(node_base + n0) * D + o_base) = r0;
    *reinterpret_cast<float4*>(out + (size_t)(node_base + n1) * D + o_base) = r1;
}

extern "C" void kernel_launch(void* const* d_in, const int* in_sizes, int n_in,
                              void* d_out, int out_size) {
    const float* x       = (const float*)d_in[0];
    const int*   lp_rows = (const int*)d_in[1];
    const int*   lp_cols = (const int*)d_in[2];
    const float* lp_vals = (const float*)d_in[3];
    const int*   hp_rows = (const int*)d_in[4];
    const int*   hp_cols = (const int*)d_in[5];
    const float* hp_vals = (const float*)d_in[6];
    const float* alpha_w = (const float*)d_in[7];
    const float* alpha_b = (const float*)d_in[8];
    const float* W       = (const float*)d_in[9];
    const float* bvec    = (const float*)d_in[10];
    float* out = (float*)d_out;

    int write_alpha = (out_size >= N_NODES * D + N_NODES) ? 1 : 0;

    zero_z_kernel<<<2048, 256>>>();
    transpose_W_kernel<<<(D * D + 255) / 256, 256>>>(W);
    alpha_kernel<<<(N_NODES * 32 + 255) / 256, 256>>>(
        x, alpha_w, alpha_b, out + (size_t)N_NODES * D, write_alpha);

    // 2*800000 edges, 1 warp each, 8 warps/block -> 200000 blocks
    edge_scatter_kernel<<<(2 * N_EDGES) / 8, 256>>>(
        x, lp_rows, lp_cols, lp_vals, hp_rows, hp_cols, hp_vals);

    const int smem_bytes = (D * D + GEMM_NODES * D) * (int)sizeof(float); // 73728
    cudaFuncSetAttribute(gemm_relu_kernel,
                         cudaFuncAttributeMaxDynamicSharedMemorySize, smem_bytes);
    gemm_relu_kernel<<<N_NODES / GEMM_NODES, 256, smem_bytes>>>(bvec, out);
}

// round 5
// speedup vs baseline: 1.7462x; 1.7462x over previous
#include <cuda_runtime.h>
#include <math.h>

#define N_NODES 50000
#define N_EDGES 800000
#define D 128
#define GEMM_NODES 16

// Scratch (device globals: no allocation allowed in kernel_launch)
__device__ float g_z[N_NODES * D];      // 25.6 MB mixed accumulator
__device__ float g_alpha[N_NODES];
__device__ float g_Wt[D * D];           // W transposed: [k][o]

__global__ void zero_z_kernel() {
    int idx = blockIdx.x * blockDim.x + threadIdx.x;
    float4* p = reinterpret_cast<float4*>(g_z);
    const int n4 = N_NODES * D / 4;
    for (int i = idx; i < n4; i += gridDim.x * blockDim.x)
        p[i] = make_float4(0.f, 0.f, 0.f, 0.f);
}

__global__ void transpose_W_kernel(const float* __restrict__ W) {
    int idx = blockIdx.x * blockDim.x + threadIdx.x;
    if (idx < D * D) {
        int k = idx / D, o = idx % D;
        g_Wt[idx] = W[o * D + k];
    }
}

// One warp per node: alpha = sigmoid(x . theta + b)
__global__ void alpha_kernel(const float* __restrict__ x,
                             const float* __restrict__ aw,
                             const float* __restrict__ ab,
                             float* __restrict__ out_alpha, int write_alpha) {
    int warp = (blockIdx.x * blockDim.x + threadIdx.x) >> 5;
    int lane = threadIdx.x & 31;
    if (warp >= N_NODES) return;
    float4 xv = *reinterpret_cast<const float4*>(x + (size_t)warp * D + lane * 4);
    float4 wv = *reinterpret_cast<const float4*>(aw + lane * 4);
    float s = xv.x * wv.x + xv.y * wv.y + xv.z * wv.z + xv.w * wv.w;
    #pragma unroll
    for (int off = 16; off; off >>= 1) s += __shfl_xor_sync(0xffffffffu, s, off);
    if (lane == 0) {
        float a = 1.f / (1.f + expf(-(s + ab[0])));
        g_alpha[warp] = a;
        if (write_alpha) out_alpha[warp] = a;
    }
}

__device__ __forceinline__ void red_add_v4(float* addr, float a, float b,
                                           float c, float d) {
    asm volatile("red.global.add.v4.f32 [%0], {%1, %2, %3, %4};"
                 :: "l"(addr), "f"(a), "f"(b), "f"(c), "f"(d)
                 : "memory");
}

// One warp per edge (both operators fused): z[row] += coef * x[col]
// coef = alpha[row]*val (lp)  or  (1-alpha[row])*val (hp)
__global__ void edge_scatter_kernel(const float* __restrict__ x,
                                    const int* __restrict__ lp_rows,
                                    const int* __restrict__ lp_cols,
                                    const float* __restrict__ lp_vals,
                                    const int* __restrict__ hp_rows,
                                    const int* __restrict__ hp_cols,
                                    const float* __restrict__ hp_vals) {
    long long warp = ((long long)blockIdx.x * blockDim.x + threadIdx.x) >> 5;
    int lane = threadIdx.x & 31;
    if (warp >= 2LL * N_EDGES) return;

    // Lane 0 loads edge metadata; broadcast to the warp.
    int row = 0, col = 0;
    float coef = 0.f;
    if (lane == 0) {
        int e; float v; bool hp;
        if (warp >= N_EDGES) {
            e = (int)(warp - N_EDGES);
            row = hp_rows[e]; col = hp_cols[e]; v = hp_vals[e]; hp = true;
        } else {
            e = (int)warp;
            row = lp_rows[e]; col = lp_cols[e]; v = lp_vals[e]; hp = false;
        }
        float a = g_alpha[row];
        coef = hp ? (1.f - a) * v : a * v;
    }
    row  = __shfl_sync(0xffffffffu, row, 0);
    col  = __shfl_sync(0xffffffffu, col, 0);
    coef = __shfl_sync(0xffffffffu, coef, 0);

    float4 xv = *reinterpret_cast<const float4*>(x + (size_t)col * D + lane * 4);
    float* zp = g_z + (size_t)row * D + lane * 4;
    red_add_v4(zp, coef * xv.x, coef * xv.y, coef * xv.z, coef * xv.w);
}

// out[n][o] = relu(sum_k z[n][k] * Wt[k][o] + b[o])
extern __shared__ float g_smem[];
__global__ void gemm_relu_kernel(const float* __restrict__ bias,
                                 float* __restrict__ out) {
    float* wt_sh = g_smem;              // 128*128 floats
    float* z_sh  = g_smem + D * D;      // 16*128 floats
    int tid = threadIdx.x;

    {
        const float4* src = reinterpret_cast<const float4*>(g_Wt);
        float4* dst = reinterpret_cast<float4*>(wt_sh);
        #pragma unroll
        for (int i = tid; i < D * D / 4; i += 256) dst[i] = src[i];
    }
    int node_base = blockIdx.x * GEMM_NODES;
    {
        const float4* src = reinterpret_cast<const float4*>(g_z + (size_t)node_base * D);
        float4* dst = reinterpret_cast<float4*>(z_sh);
        #pragma unroll
        for (int i = tid; i < GEMM_NODES * D / 4; i += 256) dst[i] = src[i];
    }
    __syncthreads();

    int o_base = (tid & 31) * 4;
    int ng = tid >> 5;
    int n0 = ng * 2, n1 = n0 + 1;
    const float* z0p = z_sh + n0 * D;
    const float* z1p = z_sh + n1 * D;

    float acc00 = 0.f, acc01 = 0.f, acc02 = 0.f, acc03 = 0.f;
    float acc10 = 0.f, acc11 = 0.f, acc12 = 0.f, acc13 = 0.f;

    #pragma unroll 8
    for (int k = 0; k < D; k++) {
        float4 w = *reinterpret_cast<const float4*>(wt_sh + k * D + o_base);
        float z0 = z0p[k], z1 = z1p[k];
        acc00 += z0 * w.x; acc01 += z0 * w.y; acc02 += z0 * w.z; acc03 += z0 * w.w;
        acc10 += z1 * w.x; acc11 += z1 * w.y; acc12 += z1 * w.z; acc13 += z1 * w.w;
    }

    float4 bv = *reinterpret_cast<const float4*>(bias + o_base);
    float4 r0, r1;
    r0.x = fmaxf(acc00 + bv.x, 0.f); r0.y = fmaxf(acc01 + bv.y, 0.f);
    r0.z = fmaxf(acc02 + bv.z, 0.f); r0.w = fmaxf(acc03 + bv.w, 0.f);
    r1.x = fmaxf(acc10 + bv.x, 0.f); r1.y = fmaxf(acc11 + bv.y, 0.f);
    r1.z = fmaxf(acc12 + bv.z, 0.f); r1.w = fmaxf(acc13 + bv.w, 0.f);

    *reinterpret_cast<float4*>(out + (size_t)(node_base + n0) * D + o_base) = r0;
    *reinterpret_cast<float4*>(out + (size_t)(node_base + n1) * D + o_base) = r1;
}

extern "C" void kernel_launch(void* const* d_in, const int* in_sizes, int n_in,
                              void* d_out, int out_size) {
    const float* x       = (const float*)d_in[0];
    const int*   lp_rows = (const int*)d_in[1];
    const int*   lp_cols = (const int*)d_in[2];
    const float* lp_vals = (const float*)d_in[3];
    const int*   hp_rows = (const int*)d_in[4];
    const int*   hp_cols = (const int*)d_in[5];
    const float* hp_vals = (const float*)d_in[6];
    const float* alpha_w = (const float*)d_in[7];
    const float* alpha_b = (const float*)d_in[8];
    const float* W       = (const float*)d_in[9];
    const float* bvec    = (const float*)d_in[10];
    float* out = (float*)d_out;

    int write_alpha = (out_size >= N_NODES * D + N_NODES) ? 1 : 0;

    zero_z_kernel<<<2048, 256>>>();
    transpose_W_kernel<<<(D * D + 255) / 256, 256>>>(W);
    alpha_kernel<<<(N_NODES * 32 + 255) / 256, 256>>>(
        x, alpha_w, alpha_b, out + (size_t)N_NODES * D, write_alpha);

    edge_scatter_kernel<<<(2 * N_EDGES) / 8, 256>>>(
        x, lp_rows, lp_cols, lp_vals, hp_rows, hp_cols, hp_vals);

    const int smem_bytes = (D * D + GEMM_NODES * D) * (int)sizeof(float); // 73728
    cudaFuncSetAttribute(gemm_relu_kernel,
                         cudaFuncAttributeMaxDynamicSharedMemorySize, smem_bytes);
    gemm_relu_kernel<<<N_NODES / GEMM_NODES, 256, smem_bytes>>>(bvec, out);
}

// round 6
// speedup vs baseline: 1.9976x; 1.1440x over previous
#include <cuda_runtime.h>
#include <math.h>

#define N_NODES 50000
#define N_EDGES 800000
#define D 128
#define GEMM_NODES 16
#define SCAN_T 1024
#define CHUNK ((N_NODES + SCAN_T - 1) / SCAN_T)   // 49

// Scratch (device globals: no allocation allowed in kernel_launch)
__device__ float g_z[N_NODES * D];          // 25.6 MB mixed accumulator
__device__ float g_alpha[N_NODES];
__device__ float g_Wt[D * D];               // W transposed: [k][o]
__device__ int   g_cnt[N_NODES];            // per-destination edge counts
__device__ int   g_off[N_NODES + 1];        // CSR offsets
__device__ int   g_cursor[N_NODES];         // binning cursors
__device__ int   g_bin_col[2 * N_EDGES];    // binned source column per slot
__device__ float g_bin_coef[2 * N_EDGES];   // binned premixed coefficient

__global__ void zero_cnt_kernel() {
    int i = blockIdx.x * blockDim.x + threadIdx.x;
    if (i < N_NODES) g_cnt[i] = 0;
}

__global__ void transpose_W_kernel(const float* __restrict__ W) {
    int idx = blockIdx.x * blockDim.x + threadIdx.x;
    if (idx < D * D) {
        int k = idx / D, o = idx % D;
        g_Wt[idx] = W[o * D + k];
    }
}

// One warp per node: alpha = sigmoid(x . theta + b)
__global__ void alpha_kernel(const float* __restrict__ x,
                             const float* __restrict__ aw,
                             const float* __restrict__ ab,
                             float* __restrict__ out_alpha, int write_alpha) {
    int warp = (blockIdx.x * blockDim.x + threadIdx.x) >> 5;
    int lane = threadIdx.x & 31;
    if (warp >= N_NODES) return;
    float4 xv = *reinterpret_cast<const float4*>(x + (size_t)warp * D + lane * 4);
    float4 wv = *reinterpret_cast<const float4*>(aw + lane * 4);
    float s = xv.x * wv.x + xv.y * wv.y + xv.z * wv.z + xv.w * wv.w;
    #pragma unroll
    for (int off = 16; off; off >>= 1) s += __shfl_xor_sync(0xffffffffu, s, off);
    if (lane == 0) {
        float a = 1.f / (1.f + expf(-(s + ab[0])));
        g_alpha[warp] = a;
        if (write_alpha) out_alpha[warp] = a;
    }
}

// Histogram destination rows over both operators.
__global__ void count_kernel(const int* __restrict__ lp_rows,
                             const int* __restrict__ hp_rows) {
    int i = blockIdx.x * blockDim.x + threadIdx.x;
    if (i < N_EDGES) atomicAdd(&g_cnt[lp_rows[i]], 1);
    else if (i < 2 * N_EDGES) atomicAdd(&g_cnt[hp_rows[i - N_EDGES]], 1);
}

// Single-block exclusive scan of g_cnt -> g_off, g_cursor.
__global__ void scan_kernel() {
    __shared__ int s_part[SCAN_T];
    int t = threadIdx.x;
    int beg = t * CHUNK;
    int end = min(beg + CHUNK, N_NODES);
    int sum = 0;
    for (int i = beg; i < end; i++) sum += g_cnt[i];
    s_part[t] = sum;
    __syncthreads();
    // Hillis-Steele inclusive scan
    for (int off = 1; off < SCAN_T; off <<= 1) {
        int v = (t >= off) ? s_part[t - off] : 0;
        __syncthreads();
        s_part[t] += v;
        __syncthreads();
    }
    int run = s_part[t] - sum;   // exclusive prefix of this thread's chunk
    for (int i = beg; i < end; i++) {
        g_off[i] = run;
        g_cursor[i] = run;
        run += g_cnt[i];
    }
    if (t == SCAN_T - 1) g_off[N_NODES] = run;
}

// Bin (col, coef) per destination; coef premixed with the alpha gate.
__global__ void bin_kernel(const int* __restrict__ lp_rows,
                           const int* __restrict__ lp_cols,
                           const float* __restrict__ lp_vals,
                           const int* __restrict__ hp_rows,
                           const int* __restrict__ hp_cols,
                           const float* __restrict__ hp_vals) {
    int i = blockIdx.x * blockDim.x + threadIdx.x;
    int row, col; float v; bool hp;
    if (i < N_EDGES) {
        row = lp_rows[i]; col = lp_cols[i]; v = lp_vals[i]; hp = false;
    } else if (i < 2 * N_EDGES) {
        int e = i - N_EDGES;
        row = hp_rows[e]; col = hp_cols[e]; v = hp_vals[e]; hp = true;
    } else return;
    float a = g_alpha[row];
    float coef = hp ? (1.f - a) * v : a * v;
    int pos = atomicAdd(&g_cursor[row], 1);
    g_bin_col[pos] = col;
    g_bin_coef[pos] = coef;
}

// Pull-mode gather: one warp per destination node, register accumulator.
__global__ void pull_kernel(const float* __restrict__ x) {
    int node = (blockIdx.x * blockDim.x + threadIdx.x) >> 5;
    int lane = threadIdx.x & 31;
    if (node >= N_NODES) return;
    int s = g_off[node];
    int e = g_off[node + 1];

    float ax = 0.f, ay = 0.f, az = 0.f, aw = 0.f;
    for (int base = s; base < e; base += 32) {
        int myi = base + lane;
        int   col  = (myi < e) ? g_bin_col[myi]  : 0;
        float coef = (myi < e) ? g_bin_coef[myi] : 0.f;
        int cnt = min(32, e - base);
        #pragma unroll 4
        for (int j = 0; j < cnt; j++) {
            int   cj = __shfl_sync(0xffffffffu, col, j);
            float fj = __shfl_sync(0xffffffffu, coef, j);
            float4 xv = *reinterpret_cast<const float4*>(
                x + (size_t)cj * D + lane * 4);
            ax = fmaf(fj, xv.x, ax);
            ay = fmaf(fj, xv.y, ay);
            az = fmaf(fj, xv.z, az);
            aw = fmaf(fj, xv.w, aw);
        }
    }
    float4 r; r.x = ax; r.y = ay; r.z = az; r.w = aw;
    *reinterpret_cast<float4*>(g_z + (size_t)node * D + lane * 4) = r;
}

// out[n][o] = relu(sum_k z[n][k] * Wt[k][o] + b[o])
extern __shared__ float g_smem[];
__global__ void gemm_relu_kernel(const float* __restrict__ bias,
                                 float* __restrict__ out) {
    float* wt_sh = g_smem;              // 128*128 floats
    float* z_sh  = g_smem + D * D;      // 16*128 floats
    int tid = threadIdx.x;

    {
        const float4* src = reinterpret_cast<const float4*>(g_Wt);
        float4* dst = reinterpret_cast<float4*>(wt_sh);
        #pragma unroll
        for (int i = tid; i < D * D / 4; i += 256) dst[i] = src[i];
    }
    int node_base = blockIdx.x * GEMM_NODES;
    {
        const float4* src = reinterpret_cast<const float4*>(g_z + (size_t)node_base * D);
        float4* dst = reinterpret_cast<float4*>(z_sh);
        #pragma unroll
        for (int i = tid; i < GEMM_NODES * D / 4; i += 256) dst[i] = src[i];
    }
    __syncthreads();

    int o_base = (tid & 31) * 4;
    int ng = tid >> 5;
    int n0 = ng * 2, n1 = n0 + 1;
    const float* z0p = z_sh + n0 * D;
    const float* z1p = z_sh + n1 * D;

    float acc00 = 0.f, acc01 = 0.f, acc02 = 0.f, acc03 = 0.f;
    float acc10 = 0.f, acc11 = 0.f, acc12 = 0.f, acc13 = 0.f;

    #pragma unroll 8
    for (int k = 0; k < D; k++) {
        float4 w = *reinterpret_cast<const float4*>(wt_sh + k * D + o_base);
        float z0 = z0p[k], z1 = z1p[k];
        acc00 += z0 * w.x; acc01 += z0 * w.y; acc02 += z0 * w.z; acc03 += z0 * w.w;
        acc10 += z1 * w.x; acc11 += z1 * w.y; acc12 += z1 * w.z; acc13 += z1 * w.w;
    }

    float4 bv = *reinterpret_cast<const float4*>(bias + o_base);
    float4 r0, r1;
    r0.x = fmaxf(acc00 + bv.x, 0.f); r0.y = fmaxf(acc01 + bv.y, 0.f);
    r0.z = fmaxf(acc02 + bv.z, 0.f); r0.w = fmaxf(acc03 + bv.w, 0.f);
    r1.x = fmaxf(acc10 + bv.x, 0.f); r1.y = fmaxf(acc11 + bv.y, 0.f);
    r1.z = fmaxf(acc12 + bv.z, 0.f); r1.w = fmaxf(acc13 + bv.w, 0.f);

    *reinterpret_cast<float4*>(out + (size_t)(node_base + n0) * D + o_base) = r0;
    *reinterpret_cast<float4*>(out + (size_t)(node_base + n1) * D + o_base) = r1;
}

extern "C" void kernel_launch(void* const* d_in, const int* in_sizes, int n_in,
                              void* d_out, int out_size) {
    const float* x       = (const float*)d_in[0];
    const int*   lp_rows = (const int*)d_in[1];
    const int*   lp_cols = (const int*)d_in[2];
    const float* lp_vals = (const float*)d_in[3];
    const int*   hp_rows = (const int*)d_in[4];
    const int*   hp_cols = (const int*)d_in[5];
    const float* hp_vals = (const float*)d_in[6];
    const float* alpha_w = (const float*)d_in[7];
    const float* alpha_b = (const float*)d_in[8];
    const float* W       = (const float*)d_in[9];
    const float* bvec    = (const float*)d_in[10];
    float* out = (float*)d_out;

    int write_alpha = (out_size >= N_NODES * D + N_NODES) ? 1 : 0;

    zero_cnt_kernel<<<(N_NODES + 255) / 256, 256>>>();
    transpose_W_kernel<<<(D * D + 255) / 256, 256>>>(W);
    alpha_kernel<<<(N_NODES * 32 + 255) / 256, 256>>>(
        x, alpha_w, alpha_b, out + (size_t)N_NODES * D, write_alpha);

    count_kernel<<<(2 * N_EDGES + 255) / 256, 256>>>(lp_rows, hp_rows);
    scan_kernel<<<1, SCAN_T>>>();
    bin_kernel<<<(2 * N_EDGES + 255) / 256, 256>>>(
        lp_rows, lp_cols, lp_vals, hp_rows, hp_cols, hp_vals);

    pull_kernel<<<(N_NODES * 32 + 255) / 256, 256>>>(x);

    const int smem_bytes = (D * D + GEMM_NODES * D) * (int)sizeof(float); // 73728
    cudaFuncSetAttribute(gemm_relu_kernel,
                         cudaFuncAttributeMaxDynamicSharedMemorySize, smem_bytes);
    gemm_relu_kernel<<<N_NODES / GEMM_NODES, 256, smem_bytes>>>(bvec, out);
}

// round 7
// speedup vs baseline: 2.2337x; 1.1182x over previous
#include <cuda_runtime.h>
#include <math.h>

#define N_NODES 50000
#define N_EDGES 800000
#define D 128
#define GEMM_NODES 32
#define SCAN_T 1024
#define CHUNK ((N_NODES + SCAN_T - 1) / SCAN_T)   // 49

// Scratch (device globals: no allocation allowed in kernel_launch)
__device__ float g_z[N_NODES * D];          // 25.6 MB mixed accumulator
__device__ float g_alpha[N_NODES];
__device__ float g_Wt[D * D];               // W transposed: [k][o]
__device__ int   g_cnt[N_NODES];            // per-destination edge counts
__device__ int   g_off[N_NODES + 1];        // CSR offsets
__device__ int   g_cursor[N_NODES];         // binning cursors
__device__ int2  g_bin[2 * N_EDGES];        // packed (col, coef-bits) per slot

__global__ void zero_cnt_kernel() {
    int i = blockIdx.x * blockDim.x + threadIdx.x;
    if (i < N_NODES) g_cnt[i] = 0;
}

__global__ void transpose_W_kernel(const float* __restrict__ W) {
    int idx = blockIdx.x * blockDim.x + threadIdx.x;
    if (idx < D * D) {
        int k = idx / D, o = idx % D;
        g_Wt[idx] = W[o * D + k];
    }
}

// One warp per node: alpha = sigmoid(x . theta + b)
__global__ void alpha_kernel(const float* __restrict__ x,
                             const float* __restrict__ aw,
                             const float* __restrict__ ab,
                             float* __restrict__ out_alpha, int write_alpha) {
    int warp = (blockIdx.x * blockDim.x + threadIdx.x) >> 5;
    int lane = threadIdx.x & 31;
    if (warp >= N_NODES) return;
    float4 xv = *reinterpret_cast<const float4*>(x + (size_t)warp * D + lane * 4);
    float4 wv = *reinterpret_cast<const float4*>(aw + lane * 4);
    float s = xv.x * wv.x + xv.y * wv.y + xv.z * wv.z + xv.w * wv.w;
    #pragma unroll
    for (int off = 16; off; off >>= 1) s += __shfl_xor_sync(0xffffffffu, s, off);
    if (lane == 0) {
        float a = 1.f / (1.f + expf(-(s + ab[0])));
        g_alpha[warp] = a;
        if (write_alpha) out_alpha[warp] = a;
    }
}

// Histogram destination rows: 8 edges per thread (4 lp + 4 hp) for MLP.
__global__ void count_kernel(const int* __restrict__ lp_rows,
                             const int* __restrict__ hp_rows) {
    int i = blockIdx.x * blockDim.x + threadIdx.x;
    if (i >= N_EDGES / 4) return;
    int4 r = reinterpret_cast<const int4*>(lp_rows)[i];
    int4 h = reinterpret_cast<const int4*>(hp_rows)[i];
    atomicAdd(&g_cnt[r.x], 1); atomicAdd(&g_cnt[r.y], 1);
    atomicAdd(&g_cnt[r.z], 1); atomicAdd(&g_cnt[r.w], 1);
    atomicAdd(&g_cnt[h.x], 1); atomicAdd(&g_cnt[h.y], 1);
    atomicAdd(&g_cnt[h.z], 1); atomicAdd(&g_cnt[h.w], 1);
}

// Single-block exclusive scan of g_cnt -> g_off, g_cursor.
__global__ void scan_kernel() {
    __shared__ int s_part[SCAN_T];
    int t = threadIdx.x;
    int beg = t * CHUNK;
    int end = min(beg + CHUNK, N_NODES);
    int sum = 0;
    for (int i = beg; i < end; i++) sum += g_cnt[i];
    s_part[t] = sum;
    __syncthreads();
    for (int off = 1; off < SCAN_T; off <<= 1) {
        int v = (t >= off) ? s_part[t - off] : 0;
        __syncthreads();
        s_part[t] += v;
        __syncthreads();
    }
    int run = s_part[t] - sum;   // exclusive prefix of this thread's chunk
    for (int i = beg; i < end; i++) {
        g_off[i] = run;
        g_cursor[i] = run;
        run += g_cnt[i];
    }
    if (t == SCAN_T - 1) g_off[N_NODES] = run;
}

// Bin packed (col, coef) per destination; 4 edges of each operator per thread.
__global__ void bin_kernel(const int* __restrict__ lp_rows,
                           const int* __restrict__ lp_cols,
                           const float* __restrict__ lp_vals,
                           const int* __restrict__ hp_rows,
                           const int* __restrict__ hp_cols,
                           const float* __restrict__ hp_vals) {
    int i = blockIdx.x * blockDim.x + threadIdx.x;
    if (i >= N_EDGES / 4) return;

    int4   lr = reinterpret_cast<const int4*>(lp_rows)[i];
    int4   lc = reinterpret_cast<const int4*>(lp_cols)[i];
    float4 lv = reinterpret_cast<const float4*>(lp_vals)[i];
    int4   hr = reinterpret_cast<const int4*>(hp_rows)[i];
    int4   hc = reinterpret_cast<const int4*>(hp_cols)[i];
    float4 hv = reinterpret_cast<const float4*>(hp_vals)[i];

    int    rs[8] = {lr.x, lr.y, lr.z, lr.w, hr.x, hr.y, hr.z, hr.w};
    int    cs[8] = {lc.x, lc.y, lc.z, lc.w, hc.x, hc.y, hc.z, hc.w};
    float  vs[8] = {lv.x, lv.y, lv.z, lv.w, hv.x, hv.y, hv.z, hv.w};

    #pragma unroll
    for (int j = 0; j < 8; j++) {
        float a = g_alpha[rs[j]];
        float coef = (j < 4) ? a * vs[j] : (1.f - a) * vs[j];
        int pos = atomicAdd(&g_cursor[rs[j]], 1);
        g_bin[pos] = make_int2(cs[j], __float_as_int(coef));
    }
}

// Pull-mode gather: one warp per destination node, register accumulator.
__global__ void pull_kernel(const float* __restrict__ x) {
    int node = (blockIdx.x * blockDim.x + threadIdx.x) >> 5;
    int lane = threadIdx.x & 31;
    if (node >= N_NODES) return;
    int s = g_off[node];
    int e = g_off[node + 1];

    float ax = 0.f, ay = 0.f, az = 0.f, aw = 0.f;
    for (int base = s; base < e; base += 32) {
        int myi = base + lane;
        int2 slot = (myi < e) ? g_bin[myi] : make_int2(0, 0);
        int cnt = min(32, e - base);
        #pragma unroll 4
        for (int j = 0; j < cnt; j++) {
            int   cj = __shfl_sync(0xffffffffu, slot.x, j);
            float fj = __int_as_float(__shfl_sync(0xffffffffu, slot.y, j));
            float4 xv = *reinterpret_cast<const float4*>(
                x + (size_t)cj * D + lane * 4);
            ax = fmaf(fj, xv.x, ax);
            ay = fmaf(fj, xv.y, ay);
            az = fmaf(fj, xv.z, az);
            aw = fmaf(fj, xv.w, aw);
        }
    }
    float4 r; r.x = ax; r.y = ay; r.z = az; r.w = aw;
    *reinterpret_cast<float4*>(g_z + (size_t)node * D + lane * 4) = r;
}

// ---- packed f32x2 helpers (sm_100+: FFMA2 only reachable via PTX) ----
__device__ __forceinline__ unsigned long long pack_dup(float z) {
    unsigned long long r;
    asm("mov.b64 %0, {%1, %1};" : "=l"(r) : "f"(z));
    return r;
}
__device__ __forceinline__ void fma2(unsigned long long& acc,
                                     unsigned long long a,
                                     unsigned long long b) {
    asm("fma.rn.f32x2 %0, %1, %2, %0;" : "+l"(acc) : "l"(a), "l"(b));
}
__device__ __forceinline__ void unpack2(unsigned long long v, float& lo, float& hi) {
    asm("mov.b64 {%0, %1}, %2;" : "=f"(lo), "=f"(hi) : "l"(v));
}

// out[n][o] = relu(sum_k z[n][k] * Wt[k][o] + b[o])
// 256 threads, 32 nodes/block. Warp w handles nodes w*4..w*4+3, lane l cols l*4..l*4+3.
// Accumulators: 4 nodes x 2 f32x2 pairs, inner loop is 8 FFMA2 per k.
extern __shared__ float g_smem[];
__global__ void gemm_relu_kernel(const float* __restrict__ bias,
                                 float* __restrict__ out) {
    float* wt_sh = g_smem;              // 128*128 floats (64 KB)
    float* z_sh  = g_smem + D * D;      // 32*128 floats (16 KB)
    int tid = threadIdx.x;
    int node_base = blockIdx.x * GEMM_NODES;
    int nodes_here = min(GEMM_NODES, N_NODES - node_base);

    {
        const float4* src = reinterpret_cast<const float4*>(g_Wt);
        float4* dst = reinterpret_cast<float4*>(wt_sh);
        #pragma unroll
        for (int i = tid; i < D * D / 4; i += 256) dst[i] = src[i];
    }
    {
        const float4* src = reinterpret_cast<const float4*>(g_z + (size_t)node_base * D);
        float4* dst = reinterpret_cast<float4*>(z_sh);
        int n4 = nodes_here * D / 4;
        for (int i = tid; i < n4; i += 256) dst[i] = src[i];
    }
    __syncthreads();

    int lane = tid & 31;
    int wrp  = tid >> 5;                // 0..7
    int o_base = lane * 4;
    int n0 = wrp * 4;
    const float* zp0 = z_sh + (n0 + 0) * D;
    const float* zp1 = z_sh + (n0 + 1) * D;
    const float* zp2 = z_sh + (n0 + 2) * D;
    const float* zp3 = z_sh + (n0 + 3) * D;

    unsigned long long a0l = 0, a0h = 0, a1l = 0, a1h = 0;
    unsigned long long a2l = 0, a2h = 0, a3l = 0, a3h = 0;

    #pragma unroll 8
    for (int k = 0; k < D; k++) {
        ulonglong2 w2 = *reinterpret_cast<const ulonglong2*>(wt_sh + k * D + o_base);
        unsigned long long z0 = pack_dup(zp0[k]);
        unsigned long long z1 = pack_dup(zp1[k]);
        unsigned long long z2 = pack_dup(zp2[k]);
        unsigned long long z3 = pack_dup(zp3[k]);
        fma2(a0l, z0, w2.x); fma2(a0h, z0, w2.y);
        fma2(a1l, z1, w2.x); fma2(a1h, z1, w2.y);
        fma2(a2l, z2, w2.x); fma2(a2h, z2, w2.y);
        fma2(a3l, z3, w2.x); fma2(a3h, z3, w2.y);
    }

    float4 bv = *reinterpret_cast<const float4*>(bias + o_base);
    unsigned long long accs[8] = {a0l, a0h, a1l, a1h, a2l, a2h, a3l, a3h};
    #pragma unroll
    for (int n = 0; n < 4; n++) {
        int node = node_base + n0 + n;
        if (node >= N_NODES) break;
        float4 r;
        unpack2(accs[n * 2 + 0], r.x, r.y);
        unpack2(accs[n * 2 + 1], r.z, r.w);
        r.x = fmaxf(r.x + bv.x, 0.f); r.y = fmaxf(r.y + bv.y, 0.f);
        r.z = fmaxf(r.z + bv.z, 0.f); r.w = fmaxf(r.w + bv.w, 0.f);
        *reinterpret_cast<float4*>(out + (size_t)node * D + o_base) = r;
    }
}

extern "C" void kernel_launch(void* const* d_in, const int* in_sizes, int n_in,
                              void* d_out, int out_size) {
    const float* x       = (const float*)d_in[0];
    const int*   lp_rows = (const int*)d_in[1];
    const int*   lp_cols = (const int*)d_in[2];
    const float* lp_vals = (const float*)d_in[3];
    const int*   hp_rows = (const int*)d_in[4];
    const int*   hp_cols = (const int*)d_in[5];
    const float* hp_vals = (const float*)d_in[6];
    const float* alpha_w = (const float*)d_in[7];
    const float* alpha_b = (const float*)d_in[8];
    const float* W       = (const float*)d_in[9];
    const float* bvec    = (const float*)d_in[10];
    float* out = (float*)d_out;

    int write_alpha = (out_size >= N_NODES * D + N_NODES) ? 1 : 0;

    zero_cnt_kernel<<<(N_NODES + 255) / 256, 256>>>();
    transpose_W_kernel<<<(D * D + 255) / 256, 256>>>(W);
    alpha_kernel<<<(N_NODES * 32 + 255) / 256, 256>>>(
        x, alpha_w, alpha_b, out + (size_t)N_NODES * D, write_alpha);

    count_kernel<<<(N_EDGES / 4 + 255) / 256, 256>>>(lp_rows, hp_rows);
    scan_kernel<<<1, SCAN_T>>>();
    bin_kernel<<<(N_EDGES / 4 + 255) / 256, 256>>>(
        lp_rows, lp_cols, lp_vals, hp_rows, hp_cols, hp_vals);

    pull_kernel<<<(N_NODES * 32 + 255) / 256, 256>>>(x);

    const int smem_bytes = (D * D + GEMM_NODES * D) * (int)sizeof(float); // 81920
    cudaFuncSetAttribute(gemm_relu_kernel,
                         cudaFuncAttributeMaxDynamicSharedMemorySize, smem_bytes);
    gemm_relu_kernel<<<(N_NODES + GEMM_NODES - 1) / GEMM_NODES, 256, smem_bytes>>>(bvec, out);
}